// round 2
// baseline (speedup 1.0000x reference)
#include <cuda_runtime.h>
#include <cuda_bf16.h>

#define NB 256
#define NT 4096
#define ND 3
#define NU 8

__device__ __forceinline__ float fsigmoid(float x) {
    // 1/(1+e^-x): FMUL+EX2 + FADD + RCP+FMUL  (~2 ulp)
    return __fdividef(1.0f, 1.0f + __expf(-x));
}
__device__ __forceinline__ float ftanh_(float x) {
    // 1 - 2/(e^{2x}+1): safe at +/-inf (e->inf gives 1, e->0 gives -1)
    return 1.0f - __fdividef(2.0f, __expf(2.0f * x) + 1.0f);
}

// One full LSTM step (t >= 1). Uses ambient locals of the kernel body.
#define STEP(T_, X0_, X1_, X2_)                                                   \
    do {                                                                          \
        tf += 1.0f;                                                               \
        float d1 = (X0_) - px0, d2 = (X1_) - px1, d3 = (X2_) - px2;               \
        px0 = (X0_); px1 = (X1_); px2 = (X2_);                                    \
        /* L2 += (L1_prev + 0.5*dx) (x) dx ; L1 += dx   (Chen, streamed) */       \
        float q0 = fmaf(0.5f, DX0, L1[0]);                                        \
        float q1 = fmaf(0.5f, d1,  L1[1]);                                        \
        float q2 = fmaf(0.5f, d2,  L1[2]);                                        \
        float q3 = fmaf(0.5f, d3,  L1[3]);                                        \
        L2[0]  = fmaf(q0, DX0, L2[0]);  L2[1]  = fmaf(q0, d1, L2[1]);             \
        L2[2]  = fmaf(q0, d2,  L2[2]);  L2[3]  = fmaf(q0, d3, L2[3]);             \
        L2[4]  = fmaf(q1, DX0, L2[4]);  L2[5]  = fmaf(q1, d1, L2[5]);             \
        L2[6]  = fmaf(q1, d2,  L2[6]);  L2[7]  = fmaf(q1, d3, L2[7]);             \
        L2[8]  = fmaf(q2, DX0, L2[8]);  L2[9]  = fmaf(q2, d1, L2[9]);             \
        L2[10] = fmaf(q2, d2,  L2[10]); L2[11] = fmaf(q2, d3, L2[11]);            \
        L2[12] = fmaf(q3, DX0, L2[12]); L2[13] = fmaf(q3, d1, L2[13]);            \
        L2[14] = fmaf(q3, d2,  L2[14]); L2[15] = fmaf(q3, d3, L2[15]);            \
        L1[0] += DX0; L1[1] += d1; L1[2] += d2; L1[3] += d3;                      \
        /* forget gate: sig_t . F, 4-way split accumulation tree */               \
        float a0 = fmaf(L1[0], F[1], F[0]);                                       \
        a0 = fmaf(L2[0],  F[5],  a0);                                             \
        a0 = fmaf(L2[4],  F[9],  a0);                                             \
        a0 = fmaf(L2[8],  F[13], a0);                                             \
        a0 = fmaf(L2[12], F[17], a0);                                             \
        float a1 = L1[1] * F[2];                                                  \
        a1 = fmaf(L2[1],  F[6],  a1);                                             \
        a1 = fmaf(L2[5],  F[10], a1);                                             \
        a1 = fmaf(L2[9],  F[14], a1);                                             \
        a1 = fmaf(L2[13], F[18], a1);                                             \
        float a2 = L1[2] * F[3];                                                  \
        a2 = fmaf(L2[2],  F[7],  a2);                                             \
        a2 = fmaf(L2[6],  F[11], a2);                                             \
        a2 = fmaf(L2[10], F[15], a2);                                             \
        a2 = fmaf(L2[14], F[19], a2);                                             \
        float a3 = L1[3] * F[4];                                                  \
        a3 = fmaf(L2[3],  F[8],  a3);                                             \
        a3 = fmaf(L2[7],  F[12], a3);                                             \
        a3 = fmaf(L2[11], F[16], a3);                                             \
        a3 = fmaf(L2[15], F[20], a3);                                             \
        float acc = (a0 + a1) + (a2 + a3);                                        \
        float norm = __fdividef(4095.0f, tf); /* sig normalized by t/(T-1) */     \
        float fg = fsigmoid(fmaf(acc, norm, bf));                                 \
        /* recurrent gates: broadcast h across the 8-lane group */                \
        float h0 = __shfl_sync(0xFFu, h, 0);                                      \
        float h1 = __shfl_sync(0xFFu, h, 1);                                      \
        float h2 = __shfl_sync(0xFFu, h, 2);                                      \
        float h3 = __shfl_sync(0xFFu, h, 3);                                      \
        float h4 = __shfl_sync(0xFFu, h, 4);                                      \
        float h5 = __shfl_sync(0xFFu, h, 5);                                      \
        float h6 = __shfl_sync(0xFFu, h, 6);                                      \
        float h7 = __shfl_sync(0xFFu, h, 7);                                      \
        float xi = fmaf((X2_), Wi[2], fmaf((X1_), Wi[1], fmaf((X0_), Wi[0], bi)));\
        float xc = fmaf((X2_), Wc[2], fmaf((X1_), Wc[1], fmaf((X0_), Wc[0], bc)));\
        float xo = fmaf((X2_), Wo[2], fmaf((X1_), Wo[1], fmaf((X0_), Wo[0], bo)));\
        float giA = fmaf(h3, Ri[3], fmaf(h2, Ri[2], fmaf(h1, Ri[1], fmaf(h0, Ri[0], xi)))); \
        float giB = fmaf(h7, Ri[7], fmaf(h6, Ri[6], fmaf(h5, Ri[5], h4 * Ri[4])));\
        float gcA = fmaf(h3, Rc[3], fmaf(h2, Rc[2], fmaf(h1, Rc[1], fmaf(h0, Rc[0], xc)))); \
        float gcB = fmaf(h7, Rc[7], fmaf(h6, Rc[6], fmaf(h5, Rc[5], h4 * Rc[4])));\
        float goA = fmaf(h3, Ro[3], fmaf(h2, Ro[2], fmaf(h1, Ro[1], fmaf(h0, Ro[0], xo)))); \
        float goB = fmaf(h7, Ro[7], fmaf(h6, Ro[6], fmaf(h5, Ro[5], h4 * Ro[4])));\
        float iv = fsigmoid(giA + giB);                                           \
        float cv = ftanh_(gcA + gcB);                                             \
        float ov = fsigmoid(goA + goB);                                           \
        c = fmaf(fg, c, iv * cv);                                                 \
        h = ov * ftanh_(c);                                                       \
        outp[(long)(T_) * NU] = h;                                                \
    } while (0)

__global__ void __launch_bounds__(32, 1) siglstm_kernel(
    const float* __restrict__ inp,   // (B, T, 3)
    const float* __restrict__ ik,    // (3, 24)
    const float* __restrict__ rk,    // (8, 24)
    const float* __restrict__ fk,    // (21, 8)
    const float* __restrict__ bias,  // (32)
    float* __restrict__ out)         // (B, T, 8)
{
    const int b = blockIdx.x;
    const int u = threadIdx.x;
    if (u >= NU) return;   // lanes 8..31 unused; shfl mask = 0xFF

    // Per-lane weight columns (one LSTM unit per lane)
    float Ri[8], Rc[8], Ro[8];
#pragma unroll
    for (int k = 0; k < 8; k++) {
        Ri[k] = rk[k * 24 + u];
        Rc[k] = rk[k * 24 + 8 + u];
        Ro[k] = rk[k * 24 + 16 + u];
    }
    float Wi[3], Wc[3], Wo[3];
#pragma unroll
    for (int d = 0; d < 3; d++) {
        Wi[d] = ik[d * 24 + u];
        Wc[d] = ik[d * 24 + 8 + u];
        Wo[d] = ik[d * 24 + 16 + u];
    }
    float F[21];
#pragma unroll
    for (int j = 0; j < 21; j++) F[j] = fk[j * 8 + u];
    const float bi = bias[u], bf = bias[8 + u], bc = bias[16 + u], bo = bias[24 + u];

    const float* __restrict__ xin = inp + (long)b * NT * ND;
    float* __restrict__ outp = out + (long)b * NT * NU + u;

    // depth-2 signature state (time-augmented path, d = 4)
    float L1[4] = {0.f, 0.f, 0.f, 0.f};
    float L2[16] = {0.f, 0.f, 0.f, 0.f, 0.f, 0.f, 0.f, 0.f,
                    0.f, 0.f, 0.f, 0.f, 0.f, 0.f, 0.f, 0.f};
    const float DX0 = 1.0f / 4095.0f;   // time increment of the augmented path

    float h, c;
    float px0, px1, px2;

    // ---- t = 0: c_prev = 0 so the forget gate is irrelevant ----
    {
        px0 = xin[0]; px1 = xin[1]; px2 = xin[2];
        float gi = fmaf(px2, Wi[2], fmaf(px1, Wi[1], fmaf(px0, Wi[0], bi)));
        float gc = fmaf(px2, Wc[2], fmaf(px1, Wc[1], fmaf(px0, Wc[0], bc)));
        float go = fmaf(px2, Wo[2], fmaf(px1, Wo[1], fmaf(px0, Wo[0], bo)));
        c = fsigmoid(gi) * ftanh_(gc);
        h = fsigmoid(go) * ftanh_(c);
        outp[0] = h;
    }

    // ---- software prefetch ring: slot(t) = (t-1) & 7, fill t = 1..8 ----
    float xb0[8], xb1[8], xb2[8];
#pragma unroll
    for (int j = 0; j < 8; j++) {
        xb0[j] = xin[(1 + j) * 3 + 0];
        xb1[j] = xin[(1 + j) * 3 + 1];
        xb2[j] = xin[(1 + j) * 3 + 2];
    }

    float tf = 0.0f;

    // ---- steady state: t = 1 .. 4088 (511 blocks of 8, static ring slots) ----
    for (int blk = 0; blk < 511; blk++) {
#pragma unroll
        for (int j = 0; j < 8; j++) {
            const int t = 1 + blk * 8 + j;
            float x0 = xb0[j], x1 = xb1[j], x2 = xb2[j];
            int tp = t + 8;
            if (tp > NT - 1) tp = NT - 1;       // clamp keeps loads in-bounds
            xb0[j] = xin[tp * 3 + 0];
            xb1[j] = xin[tp * 3 + 1];
            xb2[j] = xin[tp * 3 + 2];
            STEP(t, x0, x1, x2);
        }
    }

    // ---- epilogue: t = 4089 .. 4095 (slots j = 0..6, already prefetched) ----
#pragma unroll
    for (int j = 0; j < 7; j++) {
        const int t = 4089 + j;
        float x0 = xb0[j], x1 = xb1[j], x2 = xb2[j];
        STEP(t, x0, x1, x2);
    }
}

extern "C" void kernel_launch(void* const* d_in, const int* in_sizes, int n_in,
                              void* d_out, int out_size)
{
    const float* inp  = (const float*)d_in[0];   // inputs (256,4096,3)
    const float* ik   = (const float*)d_in[1];   // input_kernel (3,24)
    const float* rk   = (const float*)d_in[2];   // recurrent_kernel (8,24)
    const float* fk   = (const float*)d_in[3];   // forget_kernel (21,8)
    const float* bias = (const float*)d_in[4];   // bias (32)
    float* out = (float*)d_out;                  // (256,4096,8) f32

    siglstm_kernel<<<NB, 32>>>(inp, ik, rk, fk, bias, out);
}